// round 17
// baseline (speedup 1.0000x reference)
#include <cuda_runtime.h>
#include <cstdint>

// PatchTransformer R17: R16's frame (4096 x 32x8 tiles, 256 threads, 8 CTA/SM,
// multi-wave rebalancing) with the fast path pushed to WARP (row) granularity:
// warp = one 32px row; per-row ballot mask (row-exact y test, lanes 0..7 own
// patch locs, shfl in loop); empty rows take a 24-lane float4 copy; no smem,
// no syncthreads anywhere. Exact-fp replication of the reference grid_sample
// chain (rn intrinsics block FMA contraction): reference gates on mask==1.0
// and adv==0.0 equality.

#define S 1024
#define PS 256
#define NP 8

__global__ __launch_bounds__(256, 8)
void patch_transformer_kernel(const float* __restrict__ patches,   // [8,3,256,256]
                              const float* __restrict__ locs,      // [8,2]
                              const float* __restrict__ clean,     // [3,1024,1024]
                              float* __restrict__ out)             // [3,1024,1024]
{
    const int lane = threadIdx.x;              // 0..31; warp == one image row
    const int bw0  = blockIdx.x * 32;
    const int h    = blockIdx.y * 8 + threadIdx.y;
    const int w    = bw0 + lane;

    // Per-lane patch location preload (lanes 0..7 own one patch each).
    float plx = 0.0f, ply = 0.0f;
    if (lane < NP) {
        plx = __ldg(locs + 2 * lane + 0);
        ply = __ldg(locs + 2 * lane + 1);
    }
    const float ppx = 512.0f * plx;
    const float ppy = 512.0f * ply;

    // Row-exact conservative candidate mask. Exact sample coord
    // x == w - 512*lx to within <1e-3 px; a pixel can touch patch data only
    // if x in [-1,257). +-2 px margin keeps it strictly conservative.
    const bool hit = (lane < NP) &&
                     ((float)bw0        <= ppx + 258.0f) &&
                     ((float)(bw0 + 31) >= ppx - 2.0f)   &&
                     ((float)h          <= ppy + 258.0f) &&
                     ((float)h          >= ppy - 2.0f);
    unsigned cmask = __ballot_sync(0xFFFFFFFFu, hit) & 0xFFu;   // warp-uniform

    if (cmask == 0) {
        // ---- Fast path: copy this row (32px x 3ch = 24 float4), lanes 0..23.
        if (lane < 24) {
            const int c   = lane >> 3;           // channel 0..2
            const int col = (lane & 7) << 2;     // 0,4,...,28
            const int off = c * S * S + h * S + bw0 + col;
            *(float4*)(out + off) = *(const float4*)(clean + off);
        }
        return;
    }

    // ---- Patch path: exact per-pixel chain (bit-identical to reference).
    const int pix = h * S + w;
    float v0 = clean[pix];
    float v1 = clean[pix + S * S];
    float v2 = clean[pix + 2 * S * S];

    // Normalized grid coords, exact reference chain (all steps exact fp32).
    const float gx = __fadd_rn(__fmul_rn(__fmul_rn(__fadd_rn((float)w, 0.5f), 2.0f),
                                         (1.0f / 1024.0f)), -1.0f);
    const float gy = __fadd_rn(__fmul_rn(__fmul_rn(__fadd_rn((float)h, 0.5f), 2.0f),
                                         (1.0f / 1024.0f)), -1.0f);

    do {
        const int n = __ffs(cmask) - 1;   // ascending = reference paste order
        cmask &= cmask - 1;

        const float lx = __shfl_sync(0xFFFFFFFFu, plx, n);
        const float ly = __shfl_sync(0xFFFFFFFFu, ply, n);

        // Exact reference chain (bit-for-bit).
        const float gry = __fadd_rn(gy, -ly);
        const float y = __fmul_rn(__fadd_rn(__fmul_rn(__fadd_rn(gry, 1.0f), 1024.0f), -1.0f), 0.5f);
        const float y0f = floorf(y);
        const int iy0 = (int)y0f;
        if ((unsigned)(iy0 + 1) > 256u) continue;

        const float grx = __fadd_rn(gx, -lx);
        const float x = __fmul_rn(__fadd_rn(__fmul_rn(__fadd_rn(grx, 1.0f), 1024.0f), -1.0f), 0.5f);
        const float x0f = floorf(x);
        const int ix0 = (int)x0f;
        if ((unsigned)(ix0 + 1) > 256u) continue;

        const float wx1 = __fadd_rn(x, -x0f);
        const float wx0 = __fadd_rn(1.0f, -wx1);
        const float wy1 = __fadd_rn(y, -y0f);
        const float wy0 = __fadd_rn(1.0f, -wy1);

        const float w00 = __fmul_rn(wy0, wx0);
        const float w01 = __fmul_rn(wy0, wx1);
        const float w10 = __fmul_rn(wy1, wx0);
        const float w11 = __fmul_rn(wy1, wx1);

        const bool vx0 = (ix0 >= 0);
        const bool vy0 = (iy0 >= 0);
        // mask_w = left-associated sum of valid*weight, exactly as reference
        // (inside the footprint the +1 taps are always frame-valid).
        const float msum = __fadd_rn(__fadd_rn(__fadd_rn(
                               (vy0 && vx0) ? w00 : 0.0f,
                               vy0 ? w01 : 0.0f),
                               vx0 ? w10 : 0.0f),
                               w11);
        if (msum != 1.0f) continue;

        const bool cx1 = (ix0 <= PS - 2);
        const bool cy1 = (iy0 <= PS - 2);
        const bool t00v = vy0 && vx0;
        const bool t01v = vy0 && cx1;
        const bool t10v = cy1 && vx0;
        const bool t11v = cy1 && cx1;
        if (!(t00v | t01v | t10v | t11v)) continue;

        const float* P = patches + (size_t)n * 3 * PS * PS;
        const int o00 = iy0 * PS + ix0;

        #pragma unroll
        for (int c = 0; c < 3; ++c) {
            const float* B = P + c * PS * PS;
            const float t00 = t00v ? __fmul_rn(__ldg(B + o00),          w00) : 0.0f;
            const float t01 = t01v ? __fmul_rn(__ldg(B + o00 + 1),      w01) : 0.0f;
            const float t10 = t10v ? __fmul_rn(__ldg(B + o00 + PS),     w10) : 0.0f;
            const float t11 = t11v ? __fmul_rn(__ldg(B + o00 + PS + 1), w11) : 0.0f;
            const float p = __fadd_rn(__fadd_rn(__fadd_rn(t00, t01), t10), t11);
            if (p != 0.0f) {
                if (c == 0) v0 = p;
                else if (c == 1) v1 = p;
                else v2 = p;
            }
        }
    } while (cmask);

    out[pix]             = v0;
    out[pix + S * S]     = v1;
    out[pix + 2 * S * S] = v2;
}

extern "C" void kernel_launch(void* const* d_in, const int* in_sizes, int n_in,
                              void* d_out, int out_size) {
    const float* patches = (const float*)d_in[0];   // (8,3,256,256)
    const float* locs    = (const float*)d_in[1];   // (8,2)
    const float* clean   = (const float*)d_in[2];   // (3,1024,1024)
    float* out = (float*)d_out;                     // (1,3,1024,1024)

    dim3 block(32, 8);
    dim3 grid(S / 32, S / 8);   // 32 x 128 = 4096 blocks (32x8 tiles)
    patch_transformer_kernel<<<grid, block>>>(patches, locs, clean, out);
}